// round 2
// baseline (speedup 1.0000x reference)
#include <cuda_runtime.h>
#include <cuda_bf16.h>
#include <math_constants.h>

#define NMAX 50048
#define EMAX 800000
#define D    128
#define D2   256
#define MSG_EPS 1e-7f
#define SM_EPS  1e-16f
#define BN_EPS  1e-5f
#define LN_EPS  1e-5f

// ---------------- scratch (static device globals; no allocation) -------------
__device__ int   g_deg[NMAX];
__device__ int   g_offs[NMAX + 1];
__device__ int   g_cur[NMAX];
__device__ int   g_srcs[EMAX];
__device__ float g_h0[(size_t)NMAX * D];    // agg + x
__device__ float g_h1[(size_t)NMAX * D2];   // after GEMM1 (BN applied in place)
__device__ float g_h2[(size_t)NMAX * D];    // after GEMM2
__device__ float g_colsum[D2];
__device__ float g_colsq[D2];

// ---------------- CSR build --------------------------------------------------
__global__ void zero_kernel(int n) {
    int i = blockIdx.x * blockDim.x + threadIdx.x;
    if (i < n) g_deg[i] = 0;
    if (i < D2) { g_colsum[i] = 0.f; g_colsq[i] = 0.f; }
}

__global__ void hist_kernel(const int* __restrict__ dst, int e) {
    int i = blockIdx.x * blockDim.x + threadIdx.x;
    if (i < e) atomicAdd(&g_deg[dst[i]], 1);
}

// single-block exclusive scan over g_deg -> g_offs
__global__ void scan_kernel(int n) {
    __shared__ int sh[1024];
    __shared__ int carry;
    int t = threadIdx.x;
    if (t == 0) carry = 0;
    __syncthreads();
    for (int base = 0; base < n; base += 1024) {
        int v = (base + t < n) ? g_deg[base + t] : 0;
        sh[t] = v;
        __syncthreads();
        for (int off = 1; off < 1024; off <<= 1) {
            int add = (t >= off) ? sh[t - off] : 0;
            __syncthreads();
            sh[t] += add;
            __syncthreads();
        }
        int incl = sh[t];
        if (base + t < n) g_offs[base + t] = carry + (incl - v);
        __syncthreads();
        if (t == 1023) carry += sh[1023];
        __syncthreads();
    }
    if (t == 0) g_offs[n] = carry;
}

__global__ void copycur_kernel(int n) {
    int i = blockIdx.x * blockDim.x + threadIdx.x;
    if (i < n) g_cur[i] = g_offs[i];
}

__global__ void scatter_kernel(const int* __restrict__ src, const int* __restrict__ dst, int e) {
    int i = blockIdx.x * blockDim.x + threadIdx.x;
    if (i < e) {
        int pos = atomicAdd(&g_cur[dst[i]], 1);
        g_srcs[pos] = src[i];
    }
}

// ---------------- softmax aggregation (warp per node) ------------------------
__global__ void agg_kernel(const float* __restrict__ x, const float* __restrict__ t_ptr, int n) {
    int gw   = (blockIdx.x * blockDim.x + threadIdx.x) >> 5;
    int lane = threadIdx.x & 31;
    if (gw >= n) return;
    float t = *t_ptr;
    int beg = g_offs[gw], end = g_offs[gw + 1];

    float m0 = -CUDART_INF_F, m1 = m0, m2 = m0, m3 = m0;
    for (int e = beg; e < end; e++) {
        const float* xr = x + (size_t)g_srcs[e] * D;
        float v0 = fmaxf(xr[lane      ], 0.f) + MSG_EPS;
        float v1 = fmaxf(xr[lane + 32 ], 0.f) + MSG_EPS;
        float v2 = fmaxf(xr[lane + 64 ], 0.f) + MSG_EPS;
        float v3 = fmaxf(xr[lane + 96 ], 0.f) + MSG_EPS;
        m0 = fmaxf(m0, t * v0); m1 = fmaxf(m1, t * v1);
        m2 = fmaxf(m2, t * v2); m3 = fmaxf(m3, t * v3);
    }
    float d0 = 0.f, d1 = 0.f, d2 = 0.f, d3 = 0.f;
    float n0 = 0.f, n1 = 0.f, n2 = 0.f, n3 = 0.f;
    for (int e = beg; e < end; e++) {
        const float* xr = x + (size_t)g_srcs[e] * D;
        float v0 = fmaxf(xr[lane      ], 0.f) + MSG_EPS;
        float v1 = fmaxf(xr[lane + 32 ], 0.f) + MSG_EPS;
        float v2 = fmaxf(xr[lane + 64 ], 0.f) + MSG_EPS;
        float v3 = fmaxf(xr[lane + 96 ], 0.f) + MSG_EPS;
        float e0 = __expf(t * v0 - m0);
        float e1 = __expf(t * v1 - m1);
        float e2 = __expf(t * v2 - m2);
        float e3 = __expf(t * v3 - m3);
        d0 += e0; d1 += e1; d2 += e2; d3 += e3;
        n0 += e0 * v0; n1 += e1 * v1; n2 += e2 * v2; n3 += e3 * v3;
    }
    const float* xrow = x + (size_t)gw * D;
    float* h = g_h0 + (size_t)gw * D;
    h[lane      ] = n0 / (d0 + SM_EPS) + xrow[lane      ];
    h[lane + 32 ] = n1 / (d1 + SM_EPS) + xrow[lane + 32 ];
    h[lane + 64 ] = n2 / (d2 + SM_EPS) + xrow[lane + 64 ];
    h[lane + 96 ] = n3 / (d3 + SM_EPS) + xrow[lane + 96 ];
}

// ---------------- tiled fp32 GEMM body: C[M,Nc] = A[M,K] @ B[K,Nc] + bias ----
// BM=BN=64, BK=16, 16x16 threads, 4x4 microtile. K%16==0, Nc%64==0.
// NOTE: A and C are __device__ globals referenced from DEVICE code via the
// wrappers below — never passed from host (host-side symbol decay gives the
// host shadow address, which GB300's ATS dereferences silently!).
template <int K, int Nc>
__device__ __forceinline__ void gemm_body(const float* __restrict__ A,
                                          const float* __restrict__ B,
                                          const float* __restrict__ bias,
                                          float* __restrict__ C, int M) {
    __shared__ float As[64][16];
    __shared__ float Bs[16][64];
    int tx = threadIdx.x, ty = threadIdx.y;
    int tid = ty * 16 + tx;
    int row0 = blockIdx.y * 64;
    int col0 = blockIdx.x * 64;

    float acc[4][4] = {};
    for (int kk = 0; kk < K; kk += 16) {
        #pragma unroll
        for (int i = 0; i < 4; i++) {
            int li = tid + i * 256;
            int r = li >> 4, c = li & 15;
            int gr = row0 + r;
            As[r][c] = (gr < M) ? A[(size_t)gr * K + kk + c] : 0.f;
        }
        #pragma unroll
        for (int i = 0; i < 4; i++) {
            int li = tid + i * 256;
            int r = li >> 6, c = li & 63;
            Bs[r][c] = B[(size_t)(kk + r) * Nc + col0 + c];
        }
        __syncthreads();
        #pragma unroll
        for (int k = 0; k < 16; k++) {
            float4 bv = *reinterpret_cast<const float4*>(&Bs[k][tx * 4]);
            float b0 = bv.x, b1 = bv.y, b2 = bv.z, b3 = bv.w;
            #pragma unroll
            for (int i = 0; i < 4; i++) {
                float a = As[ty * 4 + i][k];
                acc[i][0] += a * b0;
                acc[i][1] += a * b1;
                acc[i][2] += a * b2;
                acc[i][3] += a * b3;
            }
        }
        __syncthreads();
    }
    #pragma unroll
    for (int i = 0; i < 4; i++) {
        int gr = row0 + ty * 4 + i;
        if (gr >= M) continue;
        #pragma unroll
        for (int j = 0; j < 4; j++) {
            int gc = col0 + tx * 4 + j;
            C[(size_t)gr * Nc + gc] = acc[i][j] + bias[gc];
        }
    }
}

__global__ void gemm1_kernel(const float* __restrict__ W1, const float* __restrict__ b1, int M) {
    gemm_body<D, D2>(g_h0, W1, b1, g_h1, M);
}

__global__ void gemm2_kernel(const float* __restrict__ W2, const float* __restrict__ b2, int M) {
    gemm_body<D2, D>(g_h1, W2, b2, g_h2, M);
}

// ---------------- BatchNorm over rows (per-column stats) ---------------------
__global__ void bn_stats_kernel(int n) {
    int col = threadIdx.x;  // 256 threads
    float s = 0.f, s2 = 0.f;
    for (int r = blockIdx.x; r < n; r += gridDim.x) {
        float v = g_h1[(size_t)r * D2 + col];
        s += v; s2 += v * v;
    }
    atomicAdd(&g_colsum[col], s);
    atomicAdd(&g_colsq[col], s2);
}

__global__ void bn_apply_kernel(const float* __restrict__ gamma,
                                const float* __restrict__ beta, int n) {
    size_t idx = (size_t)blockIdx.x * blockDim.x + threadIdx.x;
    if (idx >= (size_t)n * D2) return;
    int col = (int)(idx & (D2 - 1));
    float inv_n = 1.f / (float)n;
    float mu  = g_colsum[col] * inv_n;
    float var = g_colsq[col] * inv_n - mu * mu;
    float v = g_h1[idx];
    v = (v - mu) * rsqrtf(var + BN_EPS) * gamma[col] + beta[col];
    g_h1[idx] = fmaxf(v, 0.f);
}

// ---------------- LayerNorm + ReLU + residual (warp per row) -----------------
__global__ void ln_kernel(const float* __restrict__ x,
                          const float* __restrict__ gamma,
                          const float* __restrict__ beta,
                          float* __restrict__ out, int n) {
    int gw   = (blockIdx.x * blockDim.x + threadIdx.x) >> 5;
    int lane = threadIdx.x & 31;
    if (gw >= n) return;
    const float* h = g_h2 + (size_t)gw * D;
    float v0 = h[lane], v1 = h[lane + 32], v2 = h[lane + 64], v3 = h[lane + 96];
    float s = v0 + v1 + v2 + v3;
    #pragma unroll
    for (int o = 16; o > 0; o >>= 1) s += __shfl_xor_sync(0xffffffff, s, o);
    float mu = s * (1.f / D);
    float w0 = v0 - mu, w1 = v1 - mu, w2 = v2 - mu, w3 = v3 - mu;
    float q = w0 * w0 + w1 * w1 + w2 * w2 + w3 * w3;
    #pragma unroll
    for (int o = 16; o > 0; o >>= 1) q += __shfl_xor_sync(0xffffffff, q, o);
    float r = rsqrtf(q * (1.f / D) + LN_EPS);
    const float* xr = x + (size_t)gw * D;
    float* po = out + (size_t)gw * D;
    po[lane      ] = xr[lane      ] + fmaxf(w0 * r * gamma[lane      ] + beta[lane      ], 0.f);
    po[lane + 32 ] = xr[lane + 32 ] + fmaxf(w1 * r * gamma[lane + 32 ] + beta[lane + 32 ], 0.f);
    po[lane + 64 ] = xr[lane + 64 ] + fmaxf(w2 * r * gamma[lane + 64 ] + beta[lane + 64 ], 0.f);
    po[lane + 96 ] = xr[lane + 96 ] + fmaxf(w3 * r * gamma[lane + 96 ] + beta[lane + 96 ], 0.f);
}

// ---------------- launcher ---------------------------------------------------
extern "C" void kernel_launch(void* const* d_in, const int* in_sizes, int n_in,
                              void* d_out, int out_size) {
    const float* x        = (const float*)d_in[0];
    const int*   ei       = (const int*)  d_in[1];   // [2, E]
    const float* t_ptr    = (const float*)d_in[2];
    const float* W1       = (const float*)d_in[3];
    const float* b1       = (const float*)d_in[4];
    const float* bn_gamma = (const float*)d_in[5];
    const float* bn_beta  = (const float*)d_in[6];
    const float* W2       = (const float*)d_in[7];
    const float* b2       = (const float*)d_in[8];
    const float* ln_gamma = (const float*)d_in[9];
    const float* ln_beta  = (const float*)d_in[10];
    float* out = (float*)d_out;

    int n = in_sizes[0] / D;
    int e = in_sizes[1] / 2;
    const int* src = ei;
    const int* dst = ei + e;

    // CSR build
    zero_kernel<<<(n + 255) / 256, 256>>>(n);
    hist_kernel<<<(e + 255) / 256, 256>>>(dst, e);
    scan_kernel<<<1, 1024>>>(n);
    copycur_kernel<<<(n + 255) / 256, 256>>>(n);
    scatter_kernel<<<(e + 255) / 256, 256>>>(src, dst, e);

    // softmax aggregation + residual pre-add
    agg_kernel<<<(n * 32 + 255) / 256, 256>>>(x, t_ptr, n);

    // MLP: Lin(D,2D) -> BN -> ReLU -> Lin(2D,D)
    {
        dim3 grid(D2 / 64, (n + 63) / 64), block(16, 16);
        gemm1_kernel<<<grid, block>>>(W1, b1, n);
    }
    bn_stats_kernel<<<512, 256>>>(n);
    bn_apply_kernel<<<((size_t)n * D2 + 255) / 256, 256>>>(bn_gamma, bn_beta, n);
    {
        dim3 grid(D / 64, (n + 63) / 64), block(16, 16);
        gemm2_kernel<<<grid, block>>>(W2, b2, n);
    }

    // LayerNorm -> ReLU -> residual
    ln_kernel<<<(n * 32 + 255) / 256, 256>>>(x, ln_gamma, ln_beta, out, n);
}

// round 3
// speedup vs baseline: 1.3365x; 1.3365x over previous
#include <cuda_runtime.h>
#include <cuda_bf16.h>
#include <math_constants.h>

#define NMAX 50048
#define EMAX 800000
#define D    128
#define D2   256
#define MSG_EPS 1e-7f
#define SM_EPS  1e-16f
#define BN_EPS  1e-5f
#define LN_EPS  1e-5f

// ---------------- scratch (static device globals; no allocation) -------------
__device__ int   g_deg[NMAX];
__device__ int   g_offs[NMAX + 1];
__device__ int   g_cur[NMAX];
__device__ int   g_srcs[EMAX];
__device__ float g_h0[(size_t)NMAX * D];    // agg + x
__device__ float g_h1[(size_t)NMAX * D2];   // after GEMM1 (raw, pre-BN)
__device__ float g_colsum[D2];
__device__ float g_colsq[D2];
__device__ float g_bnscale[D2];
__device__ float g_bnshift[D2];

// ---------------- CSR build --------------------------------------------------
__global__ void zero_kernel(int n) {
    int i = blockIdx.x * blockDim.x + threadIdx.x;
    if (i < n) g_deg[i] = 0;
    if (i < D2) { g_colsum[i] = 0.f; g_colsq[i] = 0.f; }
}

__global__ void hist_kernel(const int* __restrict__ dst, int e) {
    int i = blockIdx.x * blockDim.x + threadIdx.x;
    if (i < e) atomicAdd(&g_deg[dst[i]], 1);
}

// single-block warp-shuffle exclusive scan over g_deg -> g_offs
__global__ void scan_kernel(int n) {
    __shared__ int warpsums[32];
    __shared__ int carry_sh;
    int t = threadIdx.x, lane = t & 31, w = t >> 5;
    if (t == 0) carry_sh = 0;
    __syncthreads();
    for (int base = 0; base < n; base += 1024) {
        int v = (base + t < n) ? g_deg[base + t] : 0;
        int s = v;
        #pragma unroll
        for (int o = 1; o < 32; o <<= 1) {
            int u = __shfl_up_sync(0xffffffffu, s, o);
            if (lane >= o) s += u;
        }
        if (lane == 31) warpsums[w] = s;
        __syncthreads();
        if (w == 0) {
            int ws = warpsums[lane];
            #pragma unroll
            for (int o = 1; o < 32; o <<= 1) {
                int u = __shfl_up_sync(0xffffffffu, ws, o);
                if (lane >= o) ws += u;
            }
            warpsums[lane] = ws;
        }
        __syncthreads();
        int incl = s + (w > 0 ? warpsums[w - 1] : 0);
        int carry = carry_sh;
        if (base + t < n) g_offs[base + t] = carry + incl - v;
        __syncthreads();
        if (t == 1023) carry_sh = carry + incl;
        __syncthreads();
    }
    if (t == 0) g_offs[n] = carry_sh;
}

__global__ void copycur_kernel(int n) {
    int i = blockIdx.x * blockDim.x + threadIdx.x;
    if (i < n) g_cur[i] = g_offs[i];
}

__global__ void scatter_kernel(const int* __restrict__ src, const int* __restrict__ dst, int e) {
    int i = blockIdx.x * blockDim.x + threadIdx.x;
    if (i < e) {
        int pos = atomicAdd(&g_cur[dst[i]], 1);
        g_srcs[pos] = src[i];
    }
}

// ---------------- one-pass softmax aggregation (warp per node) ---------------
// logits = t*(relu(x)+eps) are in [0, ~6]: exp() cannot overflow, and softmax
// is shift-invariant, so dropping the segment-max subtraction is exact.
__global__ void agg_kernel(const float* __restrict__ x, const float* __restrict__ t_ptr, int n) {
    int gw   = (blockIdx.x * blockDim.x + threadIdx.x) >> 5;
    int lane = threadIdx.x & 31;
    if (gw >= n) return;
    float t = *t_ptr;
    int beg = g_offs[gw], end = g_offs[gw + 1];

    float n0 = 0.f, n1 = 0.f, n2 = 0.f, n3 = 0.f;
    float d0 = 0.f, d1 = 0.f, d2 = 0.f, d3 = 0.f;
    for (int e = beg; e < end; e++) {
        const float4* xr = (const float4*)(x + (size_t)g_srcs[e] * D);
        float4 q = __ldg(xr + lane);
        float v0 = fmaxf(q.x, 0.f) + MSG_EPS;
        float v1 = fmaxf(q.y, 0.f) + MSG_EPS;
        float v2 = fmaxf(q.z, 0.f) + MSG_EPS;
        float v3 = fmaxf(q.w, 0.f) + MSG_EPS;
        float e0 = __expf(t * v0), e1 = __expf(t * v1);
        float e2 = __expf(t * v2), e3 = __expf(t * v3);
        d0 += e0; d1 += e1; d2 += e2; d3 += e3;
        n0 += e0 * v0; n1 += e1 * v1; n2 += e2 * v2; n3 += e3 * v3;
    }
    float4 xq = ((const float4*)(x + (size_t)gw * D))[lane];
    float4 h;
    h.x = n0 / (d0 + SM_EPS) + xq.x;
    h.y = n1 / (d1 + SM_EPS) + xq.y;
    h.z = n2 / (d2 + SM_EPS) + xq.z;
    h.w = n3 / (d3 + SM_EPS) + xq.w;
    ((float4*)(g_h0 + (size_t)gw * D))[lane] = h;
}

// ---------------- GEMM1: h1 = h0[M,128] @ W1[128,256] + b1 -------------------
// 128x128 tile, BK=16, 256 threads (16x16), 8x8 microtile, double-buffered.
// Epilogue: write h1 and accumulate per-column sum/sumsq for BN.
__global__ __launch_bounds__(256) void gemm1_kernel(const float* __restrict__ W1,
                                                    const float* __restrict__ b1, int M) {
    constexpr int K = D, Nc = D2, BK = 16, nT = K / BK;
    __shared__ float As[2][BK][128];
    __shared__ float Bs[2][BK][128];
    const float* A = g_h0;
    int tx = threadIdx.x, ty = threadIdx.y;
    int tid = ty * 16 + tx;
    int row0 = blockIdx.y * 128, col0 = blockIdx.x * 128;

    int arow = tid >> 2, ac4 = tid & 3;   // A: 2 float4s: rows arow, arow+64
    int brow = tid >> 5, bc4 = tid & 31;  // B: 2 float4s: k-rows brow, brow+8

    float4 ra0, ra1, rb0, rb1;
    {   // prologue load tile 0
        int g0 = row0 + arow, g1 = row0 + arow + 64;
        ra0 = (g0 < M) ? *(const float4*)(A + (size_t)g0 * K + ac4 * 4) : make_float4(0,0,0,0);
        ra1 = (g1 < M) ? *(const float4*)(A + (size_t)g1 * K + ac4 * 4) : make_float4(0,0,0,0);
        rb0 = *(const float4*)(W1 + (size_t)brow * Nc + col0 + bc4 * 4);
        rb1 = *(const float4*)(W1 + (size_t)(brow + 8) * Nc + col0 + bc4 * 4);
        As[0][ac4*4+0][arow] = ra0.x; As[0][ac4*4+1][arow] = ra0.y;
        As[0][ac4*4+2][arow] = ra0.z; As[0][ac4*4+3][arow] = ra0.w;
        As[0][ac4*4+0][arow+64] = ra1.x; As[0][ac4*4+1][arow+64] = ra1.y;
        As[0][ac4*4+2][arow+64] = ra1.z; As[0][ac4*4+3][arow+64] = ra1.w;
        *(float4*)&Bs[0][brow][bc4*4]   = rb0;
        *(float4*)&Bs[0][brow+8][bc4*4] = rb1;
    }
    __syncthreads();

    float acc[8][8] = {};
    for (int t = 0; t < nT; t++) {
        int buf = t & 1;
        if (t + 1 < nT) {
            int kk = (t + 1) * BK;
            int g0 = row0 + arow, g1 = row0 + arow + 64;
            ra0 = (g0 < M) ? *(const float4*)(A + (size_t)g0 * K + kk + ac4 * 4) : make_float4(0,0,0,0);
            ra1 = (g1 < M) ? *(const float4*)(A + (size_t)g1 * K + kk + ac4 * 4) : make_float4(0,0,0,0);
            rb0 = *(const float4*)(W1 + (size_t)(kk + brow) * Nc + col0 + bc4 * 4);
            rb1 = *(const float4*)(W1 + (size_t)(kk + brow + 8) * Nc + col0 + bc4 * 4);
        }
        #pragma unroll
        for (int k = 0; k < BK; k++) {
            float4 a0 = *(const float4*)&As[buf][k][ty*8];
            float4 a1 = *(const float4*)&As[buf][k][ty*8+4];
            float4 b0 = *(const float4*)&Bs[buf][k][tx*8];
            float4 b1 = *(const float4*)&Bs[buf][k][tx*8+4];
            float av[8] = {a0.x,a0.y,a0.z,a0.w,a1.x,a1.y,a1.z,a1.w};
            float bv[8] = {b0.x,b0.y,b0.z,b0.w,b1.x,b1.y,b1.z,b1.w};
            #pragma unroll
            for (int i = 0; i < 8; i++)
                #pragma unroll
                for (int j = 0; j < 8; j++)
                    acc[i][j] += av[i] * bv[j];
        }
        if (t + 1 < nT) {
            int nb = (t + 1) & 1;
            As[nb][ac4*4+0][arow] = ra0.x; As[nb][ac4*4+1][arow] = ra0.y;
            As[nb][ac4*4+2][arow] = ra0.z; As[nb][ac4*4+3][arow] = ra0.w;
            As[nb][ac4*4+0][arow+64] = ra1.x; As[nb][ac4*4+1][arow+64] = ra1.y;
            As[nb][ac4*4+2][arow+64] = ra1.z; As[nb][ac4*4+3][arow+64] = ra1.w;
            *(float4*)&Bs[nb][brow][bc4*4]   = rb0;
            *(float4*)&Bs[nb][brow+8][bc4*4] = rb1;
        }
        __syncthreads();
    }

    // epilogue: bias, store h1, per-column sum/sumsq -> atomics
    float bj[8];
    #pragma unroll
    for (int j = 0; j < 8; j++) bj[j] = __ldg(&b1[col0 + tx*8 + j]);
    float csum[8] = {}, csq[8] = {};
    #pragma unroll
    for (int i = 0; i < 8; i++) {
        int gr = row0 + ty*8 + i;
        if (gr < M) {
            float v[8];
            #pragma unroll
            for (int j = 0; j < 8; j++) {
                v[j] = acc[i][j] + bj[j];
                csum[j] += v[j];
                csq[j]  += v[j] * v[j];
            }
            float4* po = (float4*)(g_h1 + (size_t)gr * Nc + col0 + tx*8);
            po[0] = make_float4(v[0], v[1], v[2], v[3]);
            po[1] = make_float4(v[4], v[5], v[6], v[7]);
        }
    }
    float* red = &As[0][0][0];  // 2048 floats available
    #pragma unroll
    for (int j = 0; j < 8; j++) red[ty*128 + tx*8 + j] = csum[j];
    __syncthreads();
    if (tid < 128) {
        float s = 0.f;
        #pragma unroll
        for (int r = 0; r < 16; r++) s += red[r*128 + tid];
        atomicAdd(&g_colsum[col0 + tid], s);
    }
    __syncthreads();
    #pragma unroll
    for (int j = 0; j < 8; j++) red[ty*128 + tx*8 + j] = csq[j];
    __syncthreads();
    if (tid < 128) {
        float s = 0.f;
        #pragma unroll
        for (int r = 0; r < 16; r++) s += red[r*128 + tid];
        atomicAdd(&g_colsq[col0 + tid], s);
    }
}

// ---------------- BN finalize: per-column scale/shift ------------------------
__global__ void bnfinal_kernel(const float* __restrict__ gamma,
                               const float* __restrict__ beta, int n) {
    int c = threadIdx.x;  // 256
    float inv_n = 1.f / (float)n;
    float mu  = g_colsum[c] * inv_n;
    float var = g_colsq[c] * inv_n - mu * mu;
    float sc  = gamma[c] * rsqrtf(var + BN_EPS);
    g_bnscale[c] = sc;
    g_bnshift[c] = beta[c] - mu * sc;
}

// ---------------- GEMM2: out = x + relu(LN(relu(BN(h1)) @ W2 + b2)) ----------
// BN+ReLU applied to A on load; LN+ReLU+residual fused in epilogue (128-col
// tile spans the full D=128 row, so row stats reduce across 16 lanes).
__global__ __launch_bounds__(256) void gemm2_kernel(const float* __restrict__ W2,
                                                    const float* __restrict__ b2,
                                                    const float* __restrict__ ln_gamma,
                                                    const float* __restrict__ ln_beta,
                                                    const float* __restrict__ x,
                                                    float* __restrict__ out, int M) {
    constexpr int K = D2, Nc = D, BK = 16, nT = K / BK;
    __shared__ float As[2][BK][128];
    __shared__ float Bs[2][BK][128];
    __shared__ float s_sc[D2], s_sh[D2];
    const float* A = g_h1;
    int tx = threadIdx.x, ty = threadIdx.y;
    int tid = ty * 16 + tx;
    int row0 = blockIdx.y * 128;

    if (tid < D2) { s_sc[tid] = g_bnscale[tid]; s_sh[tid] = g_bnshift[tid]; }
    __syncthreads();

    int arow = tid >> 2, ac4 = tid & 3;
    int brow = tid >> 5, bc4 = tid & 31;

    float4 ra0, ra1, rb0, rb1;
    // transform A element: relu(BN(v)) for column kc
    #define XFRM(v, kc) fmaxf((v) * s_sc[kc] + s_sh[kc], 0.f)
    {
        int g0 = row0 + arow, g1 = row0 + arow + 64;
        ra0 = (g0 < M) ? *(const float4*)(A + (size_t)g0 * K + ac4 * 4) : make_float4(0,0,0,0);
        ra1 = (g1 < M) ? *(const float4*)(A + (size_t)g1 * K + ac4 * 4) : make_float4(0,0,0,0);
        rb0 = *(const float4*)(W2 + (size_t)brow * Nc + bc4 * 4);
        rb1 = *(const float4*)(W2 + (size_t)(brow + 8) * Nc + bc4 * 4);
        int kc = ac4 * 4;
        As[0][kc+0][arow] = XFRM(ra0.x, kc+0); As[0][kc+1][arow] = XFRM(ra0.y, kc+1);
        As[0][kc+2][arow] = XFRM(ra0.z, kc+2); As[0][kc+3][arow] = XFRM(ra0.w, kc+3);
        As[0][kc+0][arow+64] = XFRM(ra1.x, kc+0); As[0][kc+1][arow+64] = XFRM(ra1.y, kc+1);
        As[0][kc+2][arow+64] = XFRM(ra1.z, kc+2); As[0][kc+3][arow+64] = XFRM(ra1.w, kc+3);
        *(float4*)&Bs[0][brow][bc4*4]   = rb0;
        *(float4*)&Bs[0][brow+8][bc4*4] = rb1;
    }
    __syncthreads();

    float acc[8][8] = {};
    for (int t = 0; t < nT; t++) {
        int buf = t & 1;
        int kk1 = (t + 1) * BK;
        if (t + 1 < nT) {
            int g0 = row0 + arow, g1 = row0 + arow + 64;
            ra0 = (g0 < M) ? *(const float4*)(A + (size_t)g0 * K + kk1 + ac4 * 4) : make_float4(0,0,0,0);
            ra1 = (g1 < M) ? *(const float4*)(A + (size_t)g1 * K + kk1 + ac4 * 4) : make_float4(0,0,0,0);
            rb0 = *(const float4*)(W2 + (size_t)(kk1 + brow) * Nc + bc4 * 4);
            rb1 = *(const float4*)(W2 + (size_t)(kk1 + brow + 8) * Nc + bc4 * 4);
        }
        #pragma unroll
        for (int k = 0; k < BK; k++) {
            float4 a0 = *(const float4*)&As[buf][k][ty*8];
            float4 a1 = *(const float4*)&As[buf][k][ty*8+4];
            float4 b0 = *(const float4*)&Bs[buf][k][tx*8];
            float4 b1 = *(const float4*)&Bs[buf][k][tx*8+4];
            float av[8] = {a0.x,a0.y,a0.z,a0.w,a1.x,a1.y,a1.z,a1.w};
            float bv[8] = {b0.x,b0.y,b0.z,b0.w,b1.x,b1.y,b1.z,b1.w};
            #pragma unroll
            for (int i = 0; i < 8; i++)
                #pragma unroll
                for (int j = 0; j < 8; j++)
                    acc[i][j] += av[i] * bv[j];
        }
        if (t + 1 < nT) {
            int nb = (t + 1) & 1;
            int kc = kk1 + ac4 * 4;
            As[nb][(ac4*4)+0][arow] = XFRM(ra0.x, kc+0); As[nb][(ac4*4)+1][arow] = XFRM(ra0.y, kc+1);
            As[nb][(ac4*4)+2][arow] = XFRM(ra0.z, kc+2); As[nb][(ac4*4)+3][arow] = XFRM(ra0.w, kc+3);
            As[nb][(ac4*4)+0][arow+64] = XFRM(ra1.x, kc+0); As[nb][(ac4*4)+1][arow+64] = XFRM(ra1.y, kc+1);
            As[nb][(ac4*4)+2][arow+64] = XFRM(ra1.z, kc+2); As[nb][(ac4*4)+3][arow+64] = XFRM(ra1.w, kc+3);
            *(float4*)&Bs[nb][brow][bc4*4]   = rb0;
            *(float4*)&Bs[nb][brow+8][bc4*4] = rb1;
        }
        __syncthreads();
    }
    #undef XFRM

    // epilogue: bias -> LayerNorm (row stats via 16-lane shuffle) -> relu -> +x
    float bj[8], gj[8], btj[8];
    #pragma unroll
    for (int j = 0; j < 8; j++) {
        int c = tx*8 + j;
        bj[j]  = __ldg(&b2[c]);
        gj[j]  = __ldg(&ln_gamma[c]);
        btj[j] = __ldg(&ln_beta[c]);
    }
    #pragma unroll
    for (int i = 0; i < 8; i++) {
        int gr = row0 + ty*8 + i;
        float v[8];
        float rs = 0.f;
        #pragma unroll
        for (int j = 0; j < 8; j++) { v[j] = acc[i][j] + bj[j]; rs += v[j]; }
        #pragma unroll
        for (int o = 8; o > 0; o >>= 1) rs += __shfl_xor_sync(0xffffffffu, rs, o);
        float mu = rs * (1.f / D);
        float q = 0.f;
        #pragma unroll
        for (int j = 0; j < 8; j++) { float w = v[j] - mu; q += w * w; }
        #pragma unroll
        for (int o = 8; o > 0; o >>= 1) q += __shfl_xor_sync(0xffffffffu, q, o);
        float rr = rsqrtf(q * (1.f / D) + LN_EPS);
        if (gr < M) {
            const float4* xr = (const float4*)(x + (size_t)gr * D + tx*8);
            float4 x0 = xr[0], x1 = xr[1];
            float xa[8] = {x0.x,x0.y,x0.z,x0.w,x1.x,x1.y,x1.z,x1.w};
            float r8[8];
            #pragma unroll
            for (int j = 0; j < 8; j++)
                r8[j] = xa[j] + fmaxf((v[j] - mu) * rr * gj[j] + btj[j], 0.f);
            float4* po = (float4*)(out + (size_t)gr * D + tx*8);
            po[0] = make_float4(r8[0], r8[1], r8[2], r8[3]);
            po[1] = make_float4(r8[4], r8[5], r8[6], r8[7]);
        }
    }
}

// ---------------- launcher ---------------------------------------------------
extern "C" void kernel_launch(void* const* d_in, const int* in_sizes, int n_in,
                              void* d_out, int out_size) {
    const float* x        = (const float*)d_in[0];
    const int*   ei       = (const int*)  d_in[1];   // [2, E]
    const float* t_ptr    = (const float*)d_in[2];
    const float* W1       = (const float*)d_in[3];
    const float* b1       = (const float*)d_in[4];
    const float* bn_gamma = (const float*)d_in[5];
    const float* bn_beta  = (const float*)d_in[6];
    const float* W2       = (const float*)d_in[7];
    const float* b2       = (const float*)d_in[8];
    const float* ln_gamma = (const float*)d_in[9];
    const float* ln_beta  = (const float*)d_in[10];
    float* out = (float*)d_out;

    int n = in_sizes[0] / D;
    int e = in_sizes[1] / 2;
    const int* src = ei;
    const int* dst = ei + e;

    // CSR build
    zero_kernel<<<(n + 255) / 256, 256>>>(n);
    hist_kernel<<<(e + 255) / 256, 256>>>(dst, e);
    scan_kernel<<<1, 1024>>>(n);
    copycur_kernel<<<(n + 255) / 256, 256>>>(n);
    scatter_kernel<<<(e + 255) / 256, 256>>>(src, dst, e);

    // one-pass softmax aggregation + residual pre-add
    agg_kernel<<<(n * 32 + 255) / 256, 256>>>(x, t_ptr, n);

    // GEMM1 (+ bias + BN stats)
    {
        dim3 grid(D2 / 128, (n + 127) / 128), block(16, 16);
        gemm1_kernel<<<grid, block>>>(W1, b1, n);
    }
    bnfinal_kernel<<<1, D2>>>(bn_gamma, bn_beta, n);
    // GEMM2 (BN+ReLU on load; + bias + LN + ReLU + residual)
    {
        dim3 grid(D / 128, (n + 127) / 128), block(16, 16);
        gemm2_kernel<<<grid, block>>>(W2, b2, ln_gamma, ln_beta, x, out, n);
    }
}

// round 5
// speedup vs baseline: 1.7220x; 1.2885x over previous
#include <cuda_runtime.h>
#include <cuda_bf16.h>
#include <math_constants.h>
#include <cstdint>

#define NMAX 50048
#define EMAX 800000
#define D    128
#define D2   256
#define MSG_EPS 1e-7f
#define SM_EPS  1e-16f
#define BN_EPS  1e-5f
#define LN_EPS  1e-5f

// ---------------- scratch (static device globals; no allocation) -------------
__device__ int   g_deg[NMAX];
__device__ int   g_offs[NMAX + 1];
__device__ int   g_cur[NMAX];
__device__ int   g_srcs[EMAX];
__device__ float g_h0[(size_t)NMAX * D];    // agg + x
__device__ float g_h1[(size_t)NMAX * D2];   // after GEMM1 (raw, pre-BN)
__device__ float g_colsum[D2];
__device__ float g_colsq[D2];
__device__ float g_bnscale[D2];
__device__ float g_bnshift[D2];
// bf16 hi/lo images of W1^T (256 n-rows x 128 k, pitch 272B) and
// W2^T (2 phases x 128 n-rows x 128 k, pitch 272B) in exact smem layout
__device__ __align__(16) unsigned char g_W1img_hi[69632];
__device__ __align__(16) unsigned char g_W1img_lo[69632];
__device__ __align__(16) unsigned char g_W2img_hi[69632];
__device__ __align__(16) unsigned char g_W2img_lo[69632];

// ---------------- helpers ----------------------------------------------------
__device__ __forceinline__ uint32_t smem_u32(const void* p) {
    uint32_t a;
    asm("{ .reg .u64 t; cvta.to.shared.u64 t, %1; cvt.u32.u64 %0, t; }" : "=r"(a) : "l"(p));
    return a;
}
__device__ __forceinline__ void ldsm_x4(uint32_t* r, uint32_t addr) {
    asm volatile("ldmatrix.sync.aligned.m8n8.x4.shared.b16 {%0,%1,%2,%3}, [%4];"
        : "=r"(r[0]), "=r"(r[1]), "=r"(r[2]), "=r"(r[3]) : "r"(addr));
}
__device__ __forceinline__ void mma16816(float* d, const uint32_t* a, const uint32_t* b) {
    asm volatile(
        "mma.sync.aligned.m16n8k16.row.col.f32.bf16.bf16.f32 "
        "{%0,%1,%2,%3}, {%4,%5,%6,%7}, {%8,%9}, {%0,%1,%2,%3};"
        : "+f"(d[0]), "+f"(d[1]), "+f"(d[2]), "+f"(d[3])
        : "r"(a[0]), "r"(a[1]), "r"(a[2]), "r"(a[3]), "r"(b[0]), "r"(b[1]));
}
// convert 8 fp32 -> bf16 hi/lo packed uint4 each
__device__ __forceinline__ void cvt8(const float* f, uint4& hv, uint4& lv) {
    unsigned h[4], l[4];
    #pragma unroll
    for (int j = 0; j < 4; j++) {
        __nv_bfloat16 a0 = __float2bfloat16(f[2*j]);
        __nv_bfloat16 a1 = __float2bfloat16(f[2*j+1]);
        __nv_bfloat16 b0 = __float2bfloat16(f[2*j]   - __bfloat162float(a0));
        __nv_bfloat16 b1 = __float2bfloat16(f[2*j+1] - __bfloat162float(a1));
        h[j] = ((unsigned)__bfloat16_as_ushort(a1) << 16) | __bfloat16_as_ushort(a0);
        l[j] = ((unsigned)__bfloat16_as_ushort(b1) << 16) | __bfloat16_as_ushort(b0);
    }
    hv = make_uint4(h[0], h[1], h[2], h[3]);
    lv = make_uint4(l[0], l[1], l[2], l[3]);
}

// ---------------- weight image precompute ------------------------------------
// B stored n-major ([N][K], pitch 272B) so non-trans ldmatrix gives the
// .col B fragment directly.
__global__ void wconv_kernel(const float* __restrict__ W1, const float* __restrict__ W2) {
    int i = blockIdx.x * blockDim.x + threadIdx.x;
    if (i < 32768) {                          // W1^T: n<256, k<128
        int nn = i >> 7, k = i & 127;
        float w = W1[k * 256 + nn];
        __nv_bfloat16 hi = __float2bfloat16(w);
        __nv_bfloat16 lo = __float2bfloat16(w - __bfloat162float(hi));
        int off = nn * 272 + k * 2;
        *(unsigned short*)(g_W1img_hi + off) = __bfloat16_as_ushort(hi);
        *(unsigned short*)(g_W1img_lo + off) = __bfloat16_as_ushort(lo);
    } else if (i < 65536) {                   // W2^T: n<128, k<256
        int j = i - 32768;
        int nn = j >> 8, k = j & 255;
        float w = W2[k * 128 + nn];
        __nv_bfloat16 hi = __float2bfloat16(w);
        __nv_bfloat16 lo = __float2bfloat16(w - __bfloat162float(hi));
        int off = (k >> 7) * 34816 + nn * 272 + (k & 127) * 2;
        *(unsigned short*)(g_W2img_hi + off) = __bfloat16_as_ushort(hi);
        *(unsigned short*)(g_W2img_lo + off) = __bfloat16_as_ushort(lo);
    }
}

// ---------------- CSR build --------------------------------------------------
__global__ void zero_kernel(int n) {
    int i = blockIdx.x * blockDim.x + threadIdx.x;
    if (i < n) g_deg[i] = 0;
    if (i < D2) { g_colsum[i] = 0.f; g_colsq[i] = 0.f; }
}

__global__ void hist_kernel(const int* __restrict__ dst, int e) {
    int i = blockIdx.x * blockDim.x + threadIdx.x;
    if (i < e) atomicAdd(&g_deg[dst[i]], 1);
}

__global__ void scan_kernel(int n) {
    __shared__ int warpsums[32];
    __shared__ int carry_sh;
    int t = threadIdx.x, lane = t & 31, w = t >> 5;
    if (t == 0) carry_sh = 0;
    __syncthreads();
    for (int base = 0; base < n; base += 1024) {
        int v = (base + t < n) ? g_deg[base + t] : 0;
        int s = v;
        #pragma unroll
        for (int o = 1; o < 32; o <<= 1) {
            int u = __shfl_up_sync(0xffffffffu, s, o);
            if (lane >= o) s += u;
        }
        if (lane == 31) warpsums[w] = s;
        __syncthreads();
        if (w == 0) {
            int ws = warpsums[lane];
            #pragma unroll
            for (int o = 1; o < 32; o <<= 1) {
                int u = __shfl_up_sync(0xffffffffu, ws, o);
                if (lane >= o) ws += u;
            }
            warpsums[lane] = ws;
        }
        __syncthreads();
        int incl = s + (w > 0 ? warpsums[w - 1] : 0);
        int carry = carry_sh;
        if (base + t < n) { int ex = carry + incl - v; g_offs[base + t] = ex; g_cur[base + t] = ex; }
        __syncthreads();
        if (t == 1023) carry_sh = carry + incl;
        __syncthreads();
    }
    if (t == 0) g_offs[n] = carry_sh;
}

__global__ void scatter_kernel(const int* __restrict__ src, const int* __restrict__ dst, int e) {
    int i = blockIdx.x * blockDim.x + threadIdx.x;
    if (i < e) {
        int pos = atomicAdd(&g_cur[dst[i]], 1);
        g_srcs[pos] = src[i];
    }
}

// ---------------- one-pass softmax aggregation (warp per node) ---------------
__global__ void agg_kernel(const float* __restrict__ x, const float* __restrict__ t_ptr, int n) {
    int gw   = (blockIdx.x * blockDim.x + threadIdx.x) >> 5;
    int lane = threadIdx.x & 31;
    if (gw >= n) return;
    float t = *t_ptr;
    int beg = g_offs[gw], end = g_offs[gw + 1];

    float n0 = 0.f, n1 = 0.f, n2 = 0.f, n3 = 0.f;
    float d0 = 0.f, d1 = 0.f, d2 = 0.f, d3 = 0.f;
    for (int e = beg; e < end; e++) {
        const float4* xr = (const float4*)(x + (size_t)g_srcs[e] * D);
        float4 q = __ldg(xr + lane);
        float v0 = fmaxf(q.x, 0.f) + MSG_EPS;
        float v1 = fmaxf(q.y, 0.f) + MSG_EPS;
        float v2 = fmaxf(q.z, 0.f) + MSG_EPS;
        float v3 = fmaxf(q.w, 0.f) + MSG_EPS;
        float e0 = __expf(t * v0), e1 = __expf(t * v1);
        float e2 = __expf(t * v2), e3 = __expf(t * v3);
        d0 += e0; d1 += e1; d2 += e2; d3 += e3;
        n0 += e0 * v0; n1 += e1 * v1; n2 += e2 * v2; n3 += e3 * v3;
    }
    float4 xq = ((const float4*)(x + (size_t)gw * D))[lane];
    float4 h;
    h.x = n0 / (d0 + SM_EPS) + xq.x;
    h.y = n1 / (d1 + SM_EPS) + xq.y;
    h.z = n2 / (d2 + SM_EPS) + xq.z;
    h.w = n3 / (d3 + SM_EPS) + xq.w;
    ((float4*)(g_h0 + (size_t)gw * D))[lane] = h;
}

// ---------------- GEMM1 (mma.sync bf16 3x): h1 = h0 @ W1 + b1 ----------------
// CTA: 128 rows x N=256, K=128. pitch 272B rows (conflict-free ldmatrix).
#define G1_AHI  0
#define G1_ALO  34816
#define G1_BHI  69632
#define G1_BLO  139264
#define G1_BIAS 208896
#define G1_SMEM 209920

__global__ __launch_bounds__(256) void gemm1_mma(const float* __restrict__ b1, int M) {
    extern __shared__ char smem[];
    uint32_t sb = smem_u32(smem);
    int tid = threadIdx.x, w = tid >> 5, lane = tid & 31;
    int row0 = blockIdx.x * 128;
    float* b1s = (float*)(smem + G1_BIAS);
    b1s[tid] = __ldg(&b1[tid]);

    // A tile: fp32 -> bf16 hi/lo split
    for (int u = tid; u < 2048; u += 256) {
        int m = u >> 4, g = u & 15;
        const float4* ar = (const float4*)(g_h0 + ((size_t)(row0 + m) << 7) + (g << 3));
        float4 q0 = ar[0], q1 = ar[1];
        float f[8] = {q0.x, q0.y, q0.z, q0.w, q1.x, q1.y, q1.z, q1.w};
        uint4 hv, lv; cvt8(f, hv, lv);
        int off = m * 272 + g * 16;
        *(uint4*)(smem + G1_AHI + off) = hv;
        *(uint4*)(smem + G1_ALO + off) = lv;
    }
    // B tiles: plain copies of precomputed images
    {
        const uint4* shh = (const uint4*)g_W1img_hi;
        const uint4* sll = (const uint4*)g_W1img_lo;
        uint4* dh = (uint4*)(smem + G1_BHI);
        uint4* dl = (uint4*)(smem + G1_BLO);
        for (int u = tid; u < 4352; u += 256) { dh[u] = shh[u]; dl[u] = sll[u]; }
    }
    __syncthreads();

    int m0 = (w & 1) * 64, n0 = (w >> 1) * 64;
    int lr = lane & 7, mid = lane >> 3;
    uint32_t aoff = (uint32_t)((m0 + lr + ((mid & 1) << 3)) * 272 + ((mid >> 1) << 4));
    uint32_t boff = (uint32_t)((n0 + lr + ((mid >> 1) << 3)) * 272 + ((mid & 1) << 4));
    uint32_t aHb = sb + G1_AHI + aoff, aLb = sb + G1_ALO + aoff;
    uint32_t bHb = sb + G1_BHI + boff, bLb = sb + G1_BLO + boff;

    float acc[4][8][4];
    #pragma unroll
    for (int i = 0; i < 4; i++)
        #pragma unroll
        for (int j = 0; j < 8; j++)
            #pragma unroll
            for (int q = 0; q < 4; q++) acc[i][j][q] = 0.f;

    #pragma unroll
    for (int ks = 0; ks < 8; ks++) {
        uint32_t kb = ks << 5;
        uint32_t aH[4][4], aL[4][4];
        #pragma unroll
        for (int mb = 0; mb < 4; mb++) {
            ldsm_x4(aH[mb], aHb + mb * 4352 + kb);
            ldsm_x4(aL[mb], aLb + mb * 4352 + kb);
        }
        #pragma unroll
        for (int nbp = 0; nbp < 4; nbp++) {
            uint32_t bh[4], bl[4];
            ldsm_x4(bh, bHb + nbp * 4352 + kb);
            ldsm_x4(bl, bLb + nbp * 4352 + kb);
            #pragma unroll
            for (int mb = 0; mb < 4; mb++) {
                mma16816(acc[mb][2*nbp],     aH[mb], bh);
                mma16816(acc[mb][2*nbp],     aH[mb], bl);
                mma16816(acc[mb][2*nbp],     aL[mb], bh);
                mma16816(acc[mb][2*nbp + 1], aH[mb], bh + 2);
                mma16816(acc[mb][2*nbp + 1], aH[mb], bl + 2);
                mma16816(acc[mb][2*nbp + 1], aL[mb], bh + 2);
            }
        }
    }

    // epilogue: + bias, direct stores (rows beyond M land in NMAX padding)
    int mtop = row0 + m0 + (lane >> 2);
    int nc = n0 + 2 * (lane & 3);
    #pragma unroll
    for (int mb = 0; mb < 4; mb++) {
        #pragma unroll
        for (int nb = 0; nb < 8; nb++) {
            int n = nc + nb * 8;
            float bv0 = b1s[n], bv1 = b1s[n + 1];
            size_t r1 = (size_t)(mtop + mb * 16) * 256 + n;
            *(float2*)(g_h1 + r1)            = make_float2(acc[mb][nb][0] + bv0, acc[mb][nb][1] + bv1);
            *(float2*)(g_h1 + r1 + 8 * 256)  = make_float2(acc[mb][nb][2] + bv0, acc[mb][nb][3] + bv1);
        }
    }
}

// ---------------- BN stats + finalize ----------------------------------------
__global__ void bn_stats_kernel(int n) {
    int col = threadIdx.x;
    float s = 0.f, s2 = 0.f;
    for (int r = blockIdx.x; r < n; r += gridDim.x) {
        float v = g_h1[(size_t)r * D2 + col];
        s += v; s2 += v * v;
    }
    atomicAdd(&g_colsum[col], s);
    atomicAdd(&g_colsq[col], s2);
}

__global__ void bnfinal_kernel(const float* __restrict__ gamma,
                               const float* __restrict__ beta, int n) {
    int c = threadIdx.x;
    float inv_n = 1.f / (float)n;
    float mu  = g_colsum[c] * inv_n;
    float var = g_colsq[c] * inv_n - mu * mu;
    float sc  = gamma[c] * rsqrtf(var + BN_EPS);
    g_bnscale[c] = sc;
    g_bnshift[c] = beta[c] - mu * sc;
}

// ---------------- GEMM2: out = x + relu(LN(relu(BN(h1)) @ W2 + b2)) ----------
// CTA 128x128, K=256 in 2 phases. BN+ReLU fused into A conversion; LN+ReLU+
// residual fused in epilogue via smem C staging (row per thread, no shuffles).
#define G2_AHI   0
#define G2_ALO   34816
#define G2_BHI   69632
#define G2_BLO   104448
#define G2_CST   69632      /* reuse B region: 128 x 132 floats = 67584 */
#define G2_CONST 139264     /* sc256|sh256|b2 128|lg 128|lb 128 */
#define G2_SMEM  142848

__global__ __launch_bounds__(256) void gemm2_mma(const float* __restrict__ b2,
                                                 const float* __restrict__ ln_gamma,
                                                 const float* __restrict__ ln_beta,
                                                 const float* __restrict__ x,
                                                 float* __restrict__ out, int M) {
    extern __shared__ char smem[];
    uint32_t sb = smem_u32(smem);
    int tid = threadIdx.x, w = tid >> 5, lane = tid & 31;
    int row0 = blockIdx.x * 128;

    float* s_sc = (float*)(smem + G2_CONST);
    float* s_sh = s_sc + 256;
    float* s_b2 = s_sh + 256;
    float* s_lg = s_b2 + 128;
    float* s_lb = s_lg + 128;
    s_sc[tid] = g_bnscale[tid];
    s_sh[tid] = g_bnshift[tid];
    if (tid < 128) {
        s_b2[tid] = __ldg(&b2[tid]);
        s_lg[tid] = __ldg(&ln_gamma[tid]);
        s_lb[tid] = __ldg(&ln_beta[tid]);
    }
    __syncthreads();

    int m0 = (w & 1) * 64, n0 = (w >> 1) * 32;
    int lr = lane & 7, mid = lane >> 3;
    uint32_t aoff = (uint32_t)((m0 + lr + ((mid & 1) << 3)) * 272 + ((mid >> 1) << 4));
    uint32_t boff = (uint32_t)((n0 + lr + ((mid >> 1) << 3)) * 272 + ((mid & 1) << 4));
    uint32_t aHb = sb + G2_AHI + aoff, aLb = sb + G2_ALO + aoff;
    uint32_t bHb = sb + G2_BHI + boff, bLb = sb + G2_BLO + boff;

    float acc[4][4][4];
    #pragma unroll
    for (int i = 0; i < 4; i++)
        #pragma unroll
        for (int j = 0; j < 4; j++)
            #pragma unroll
            for (int q = 0; q < 4; q++) acc[i][j][q] = 0.f;

    for (int p = 0; p < 2; p++) {
        // A: relu(BN(h1)) for k-cols [128p, 128p+128)
        for (int u = tid; u < 2048; u += 256) {
            int m = u >> 4, g = u & 15;
            int kc = (p << 7) + (g << 3);
            const float4* hr = (const float4*)(g_h1 + (size_t)(row0 + m) * 256 + kc);
            float4 q0 = hr[0], q1 = hr[1];
            float f[8] = {q0.x, q0.y, q0.z, q0.w, q1.x, q1.y, q1.z, q1.w};
            #pragma unroll
            for (int j = 0; j < 8; j++)
                f[j] = fmaxf(fmaf(f[j], s_sc[kc + j], s_sh[kc + j]), 0.f);
            uint4 hv, lv; cvt8(f, hv, lv);
            int off = m * 272 + g * 16;
            *(uint4*)(smem + G2_AHI + off) = hv;
            *(uint4*)(smem + G2_ALO + off) = lv;
        }
        {
            const uint4* shh = (const uint4*)(g_W2img_hi + p * 34816);
            const uint4* sll = (const uint4*)(g_W2img_lo + p * 34816);
            uint4* dh = (uint4*)(smem + G2_BHI);
            uint4* dl = (uint4*)(smem + G2_BLO);
            for (int u = tid; u < 2176; u += 256) { dh[u] = shh[u]; dl[u] = sll[u]; }
        }
        __syncthreads();

        #pragma unroll
        for (int ks = 0; ks < 8; ks++) {
            uint32_t kb = ks << 5;
            uint32_t aH[4][4], aL[4][4];
            #pragma unroll
            for (int mb = 0; mb < 4; mb++) {
                ldsm_x4(aH[mb], aHb + mb * 4352 + kb);
                ldsm_x4(aL[mb], aLb + mb * 4352 + kb);
            }
            #pragma unroll
            for (int nbp = 0; nbp < 2; nbp++) {
                uint32_t bh[4], bl[4];
                ldsm_x4(bh, bHb + nbp * 4352 + kb);
                ldsm_x4(bl, bLb + nbp * 4352 + kb);
                #pragma unroll
                for (int mb = 0; mb < 4; mb++) {
                    mma16816(acc[mb][2*nbp],     aH[mb], bh);
                    mma16816(acc[mb][2*nbp],     aH[mb], bl);
                    mma16816(acc[mb][2*nbp],     aL[mb], bh);
                    mma16816(acc[mb][2*nbp + 1], aH[mb], bh + 2);
                    mma16816(acc[mb][2*nbp + 1], aH[mb], bl + 2);
                    mma16816(acc[mb][2*nbp + 1], aL[mb], bh + 2);
                }
            }
        }
        __syncthreads();   // protect smem before next phase / C staging
    }

    // stage C into smem (pitch 132 floats)
    float* Cs = (float*)(smem + G2_CST);
    {
        int mtop = m0 + (lane >> 2), nc = n0 + 2 * (lane & 3);
        #pragma unroll
        for (int mb = 0; mb < 4; mb++) {
            #pragma unroll
            for (int nb = 0; nb < 4; nb++) {
                int n = nc + nb * 8;
                int rr = mtop + mb * 16;
                *(float2*)(Cs + rr * 132 + n)       = make_float2(acc[mb][nb][0], acc[mb][nb][1]);
                *(float2*)(Cs + (rr + 8) * 132 + n) = make_float2(acc[mb][nb][2], acc[mb][nb][3]);
            }
        }
    }
    __syncthreads();

    // fused LN + relu + residual: one thread per row
    if (tid < 128) {
        int grow = row0 + tid;
        const float* cr = Cs + tid * 132;
        float sum = 0.f, sq = 0.f;
        #pragma unroll
        for (int c = 0; c < 128; c += 4) {
            float4 q = *(const float4*)(cr + c);
            float v0 = q.x + s_b2[c], v1 = q.y + s_b2[c+1];
            float v2 = q.z + s_b2[c+2], v3 = q.w + s_b2[c+3];
            sum += v0 + v1 + v2 + v3;
            sq  += v0*v0 + v1*v1 + v2*v2 + v3*v3;
        }
        float mu = sum * (1.f / D);
        float var = sq * (1.f / D) - mu * mu;
        float rr = rsqrtf(var + LN_EPS);
        if (grow < M) {
            const float4* xr = (const float4*)(x + (size_t)grow * D);
            float4* po = (float4*)(out + (size_t)grow * D);
            #pragma unroll
            for (int c = 0; c < 128; c += 4) {
                float4 q = *(const float4*)(cr + c);
                float4 xv = __ldg(xr + (c >> 2));
                float4 o;
                o.x = xv.x + fmaxf((q.x + s_b2[c]   - mu) * rr * s_lg[c]   + s_lb[c],   0.f);
                o.y = xv.y + fmaxf((q.y + s_b2[c+1] - mu) * rr * s_lg[c+1] + s_lb[c+1], 0.f);
                o.z = xv.z + fmaxf((q.z + s_b2[c+2] - mu) * rr * s_lg[c+2] + s_lb[c+2], 0.f);
                o.w = xv.w + fmaxf((q.w + s_b2[c+3] - mu) * rr * s_lg[c+3] + s_lb[c+3], 0.f);
                po[c >> 2] = o;
            }
        }
    }
}

// ---------------- launcher ---------------------------------------------------
extern "C" void kernel_launch(void* const* d_in, const int* in_sizes, int n_in,
                              void* d_out, int out_size) {
    const float* x        = (const float*)d_in[0];
    const int*   ei       = (const int*)  d_in[1];
    const float* t_ptr    = (const float*)d_in[2];
    const float* W1       = (const float*)d_in[3];
    const float* b1       = (const float*)d_in[4];
    const float* bn_gamma = (const float*)d_in[5];
    const float* bn_beta  = (const float*)d_in[6];
    const float* W2       = (const float*)d_in[7];
    const float* b2       = (const float*)d_in[8];
    const float* ln_gamma = (const float*)d_in[9];
    const float* ln_beta  = (const float*)d_in[10];
    float* out = (float*)d_out;

    int n = in_sizes[0] / D;
    int e = in_sizes[1] / 2;
    const int* src = ei;
    const int* dst = ei + e;
    int nb = (n + 127) / 128;

    cudaFuncSetAttribute(gemm1_mma, cudaFuncAttributeMaxDynamicSharedMemorySize, G1_SMEM);
    cudaFuncSetAttribute(gemm2_mma, cudaFuncAttributeMaxDynamicSharedMemorySize, G2_SMEM);

    wconv_kernel<<<256, 256>>>(W1, W2);
    zero_kernel<<<(n + 255) / 256, 256>>>(n);
    hist_kernel<<<(e + 255) / 256, 256>>>(dst, e);
    scan_kernel<<<1, 1024>>>(n);
    scatter_kernel<<<(e + 255) / 256, 256>>>(src, dst, e);
    agg_kernel<<<(n * 32 + 255) / 256, 256>>>(x, t_ptr, n);

    gemm1_mma<<<nb, 256, G1_SMEM>>>(b1, n);
    bn_stats_kernel<<<512, 256>>>(n);
    bnfinal_kernel<<<1, D2>>>(bn_gamma, bn_beta, n);
    gemm2_mma<<<nb, 256, G2_SMEM>>>(b2, ln_gamma, ln_beta, x, out, n);
}